// round 5
// baseline (speedup 1.0000x reference)
#include <cuda_runtime.h>
#include <math.h>

#define N_NODES 16384
#define N_EDGES 262144
#define H 128
#define F 128
#define G 50
#define GP 52          // padded gaussians (even)
#define L 6
#define NGRAPH 16
#define TE 32          // edges per tile (16 pairs)
#define TN 32          // nodes per tile (k_xh)
#define TNU 64         // nodes per tile (k_update)
#define NT 256         // threads per block (2 groups x 128 channels)
#define NPAIR 8        // pairs per thread (k_edge / k_xh)
#define NPAIRU 16      // pairs per thread (k_update)

// ---------------- device scratch ----------------
__device__ float g_ea[(size_t)N_EDGES * GP];   // pair-interleaved tiles
__device__ float g_C[N_EDGES];
__device__ float g_h[(size_t)N_NODES * H];
__device__ float g_xh[(size_t)N_NODES * F];
__device__ float g_agg[(size_t)N_NODES * F];

typedef unsigned long long u64;

__device__ __forceinline__ float ssp(float x) {
    return log1pf(__expf(-fabsf(x))) + fmaxf(x, 0.0f) - 0.69314718055994531f;
}
__device__ __forceinline__ u64 dup2(float w) {
    u64 d; asm("mov.b64 %0, {%1, %1};" : "=l"(d) : "f"(w)); return d;
}
__device__ __forceinline__ u64 pack2(float lo, float hi) {
    u64 d; asm("mov.b64 %0, {%1, %2};" : "=l"(d) : "f"(lo), "f"(hi)); return d;
}
__device__ __forceinline__ void unpack2(u64 v, float& lo, float& hi) {
    asm("mov.b64 {%0, %1}, %2;" : "=f"(lo), "=f"(hi) : "l"(v));
}
__device__ __forceinline__ void fma2(u64& d, u64 a, u64 b) {
    asm("fma.rn.f32x2 %0, %1, %2, %0;" : "+l"(d) : "l"(a), "l"(b));
}

// ---------------- init: h = emb[z] ----------------
__global__ void k_init_h(const int* __restrict__ z, const float* __restrict__ emb) {
    int i = blockIdx.x * blockDim.x + threadIdx.x;
    if (i < N_NODES * H) {
        int n = i >> 7, j = i & 127;
        g_h[i] = emb[z[n] * H + j];
    }
}

// ---------------- geometry: ew, C, ea (pair-interleaved tile layout) ----------------
// tile t (32 edges): floats t*1664 + p*104 + k2*4 + (k&1)*2 + m
//   where local edge le = 2p+m, gaussian k = 2*k2 + ((q>>1)), q = idx&3
__global__ void k_geom(const float* __restrict__ pos, const int* __restrict__ ei) {
    __shared__ float ew_sh[128];
    int e = blockIdx.x * 128 + threadIdx.x;
    const int* row = ei;
    const int* col = ei + N_EDGES;
    int r = row[e], c = col[e];
    float dx = pos[r * 3 + 0] - pos[c * 3 + 0];
    float dy = pos[r * 3 + 1] - pos[c * 3 + 1];
    float dz = pos[r * 3 + 2] - pos[c * 3 + 2];
    dx -= rintf(dx * 0.2f) * 5.0f;
    dy -= rintf(dy * 0.2f) * 5.0f;
    dz -= rintf(dz * 0.2f) * 5.0f;
    float ew = sqrtf(dx * dx + dy * dy + dz * dz);
    ew_sh[threadIdx.x] = ew;
    float Cv = (ew < 10.0f) ? 0.5f * (cosf(ew * 0.31415926535897932f) + 1.0f) : 0.0f;
    g_C[e] = Cv;
    __syncthreads();
    const float step = 10.0f / 49.0f;
    const float coeff = -0.5f / (step * step);
    size_t base = (size_t)blockIdx.x * 128 * GP;
    for (int i = threadIdx.x; i < 128 * GP; i += 128) {
        int t_loc = i / (TE * GP);
        int rem = i - t_loc * (TE * GP);
        int p = rem / (2 * GP);
        int r2 = rem - p * (2 * GP);
        int k2 = r2 >> 2;
        int q = r2 & 3;
        int k = 2 * k2 + (q >> 1);
        int m = q & 1;
        int le = t_loc * TE + p * 2 + m;
        float v = 0.0f;
        if (k < G) {
            float d = ew_sh[le] - (float)k * step;
            v = __expf(coeff * d * d);
        }
        g_ea[base + i] = v;
    }
}

// ---------------- xh = h @ cf_w1[l]; zero agg ----------------
#define SMEM_XH ((TN * H + F * F) * 4)
__global__ __launch_bounds__(NT, 2) void k_xh(const float* __restrict__ w) {
    extern __shared__ float sm[];
    float* tile = sm;               // TN*H = 4096 floats, pair-interleaved
    float* ws = tile + TN * H;      // F*F
    int tid = threadIdx.x;
    int j = tid & 127;
    int grp = tid >> 7;
    int p0 = grp * NPAIR;
    for (int i = tid; i < F * F; i += NT) ws[i] = w[i];
    __syncthreads();
    const int ntiles = N_NODES / TN;
    for (int t = blockIdx.x; t < ntiles; t += gridDim.x) {
        int n0 = t * TN;
        for (int idx = tid; idx < TN * H; idx += NT) {
            int n = idx >> 7, k = idx & 127;
            int p = n >> 1, m = n & 1;
            tile[p * (2 * H) + 2 * k + m] = g_h[(size_t)n0 * H + idx];
        }
        __syncthreads();
        u64 acc[NPAIR];
        #pragma unroll
        for (int p = 0; p < NPAIR; p++) acc[p] = 0ULL;
        const ulonglong2* a2 = (const ulonglong2*)tile;   // [16][H/2]
        #pragma unroll 1
        for (int k2 = 0; k2 < H / 2; k2++) {
            u64 wk0 = dup2(ws[(2 * k2 + 0) * F + j]);
            u64 wk1 = dup2(ws[(2 * k2 + 1) * F + j]);
            #pragma unroll
            for (int p = 0; p < NPAIR; p++) {
                ulonglong2 a = a2[(p0 + p) * (H / 2) + k2];
                fma2(acc[p], a.x, wk0);
                fma2(acc[p], a.y, wk1);
            }
        }
        #pragma unroll
        for (int p = 0; p < NPAIR; p++) {
            float lo, hi; unpack2(acc[p], lo, hi);
            int n_g = n0 + (p0 + p) * 2;
            g_xh[(size_t)n_g * F + j] = lo;
            g_xh[(size_t)(n_g + 1) * F + j] = hi;
            g_agg[(size_t)n_g * F + j] = 0.0f;
            g_agg[(size_t)(n_g + 1) * F + j] = 0.0f;
        }
        __syncthreads();
    }
}

// ---------------- fused edge kernel (packed f32x2) ----------------
#define SMEM_EDGE ((TE * F + GP * F + F * F + 2 * F + 2 * TE) * 4)
__global__ __launch_bounds__(NT, 2) void k_edge(
    const float* __restrict__ w1, const float* __restrict__ b1,
    const float* __restrict__ w2, const float* __restrict__ b2,
    const int* __restrict__ ei)
{
    extern __shared__ float sm[];
    float* tile = sm;               // union: ea tile 1664 f | t tile 4096 f
    float* w1s = tile + TE * F;     // GP*F
    float* w2s = w1s + GP * F;      // F*F
    float* b1s = w2s + F * F;       // F
    float* b2s = b1s + F;           // F
    int* sRow = (int*)(b2s + F);    // TE
    int* sCol = sRow + TE;          // TE
    int tid = threadIdx.x;
    int j = tid & 127;
    int grp = tid >> 7;
    int p0 = grp * NPAIR;
    for (int i = tid; i < GP * F; i += NT) w1s[i] = (i < G * F) ? w1[i] : 0.0f;
    for (int i = tid; i < F * F; i += NT) w2s[i] = w2[i];
    if (tid < F) { b1s[tid] = b1[tid]; b2s[tid] = b2[tid]; }
    const int* row = ei;
    const int* col = ei + N_EDGES;
    __syncthreads();
    float bias1 = b1s[j], bias2 = b2s[j];
    const int ntiles = N_EDGES / TE;
    for (int t = blockIdx.x; t < ntiles; t += gridDim.x) {
        int e0 = t * TE;
        {   // stage ea tile (already pair-interleaved, contiguous)
            const float4* src = (const float4*)(g_ea + (size_t)t * (TE * GP));
            float4* dst = (float4*)tile;
            for (int i = tid; i < (TE * GP) / 4; i += NT) dst[i] = src[i];
        }
        if (tid < TE) { sRow[tid] = row[e0 + tid]; sCol[tid] = col[e0 + tid]; }
        __syncthreads();
        u64 acc[NPAIR];
        u64 binit = dup2(bias1);
        #pragma unroll
        for (int p = 0; p < NPAIR; p++) acc[p] = binit;
        const ulonglong2* ea2 = (const ulonglong2*)tile;   // [16][GP/2]
        #pragma unroll 1
        for (int k2 = 0; k2 < GP / 2; k2++) {
            u64 wk0 = dup2(w1s[(2 * k2 + 0) * F + j]);
            u64 wk1 = dup2(w1s[(2 * k2 + 1) * F + j]);
            #pragma unroll
            for (int p = 0; p < NPAIR; p++) {
                ulonglong2 a = ea2[(p0 + p) * (GP / 2) + k2];
                fma2(acc[p], a.x, wk0);
                fma2(acc[p], a.y, wk1);
            }
        }
        __syncthreads();   // all GEMM1 reads done before overwrite
        u64* tl2 = (u64*)tile;      // [16][F] packed pairs
        #pragma unroll
        for (int p = 0; p < NPAIR; p++) {
            float lo, hi; unpack2(acc[p], lo, hi);
            tl2[(p0 + p) * F + j] = pack2(ssp(lo), ssp(hi));
        }
        __syncthreads();
        u64 binit2 = dup2(bias2);
        #pragma unroll
        for (int p = 0; p < NPAIR; p++) acc[p] = binit2;
        const ulonglong2* t2 = (const ulonglong2*)tile;    // [16][F/2]
        #pragma unroll 1
        for (int k2 = 0; k2 < F / 2; k2++) {
            u64 wk0 = dup2(w2s[(2 * k2 + 0) * F + j]);
            u64 wk1 = dup2(w2s[(2 * k2 + 1) * F + j]);
            #pragma unroll
            for (int p = 0; p < NPAIR; p++) {
                ulonglong2 a = t2[(p0 + p) * (F / 2) + k2];
                fma2(acc[p], a.x, wk0);
                fma2(acc[p], a.y, wk1);
            }
        }
        // epilogue: gather xh[row], modulate by C, scatter-add to agg[col]
        #pragma unroll
        for (int p = 0; p < NPAIR; p++) {
            int le = (p0 + p) * 2;
            float2 Cc = *(const float2*)&g_C[e0 + le];
            float lo, hi; unpack2(acc[p], lo, hi);
            float W0 = lo * Cc.x, W1 = hi * Cc.y;
            int r0 = sRow[le], r1 = sRow[le + 1];
            int c0 = sCol[le], c1 = sCol[le + 1];
            atomicAdd(&g_agg[(size_t)c0 * F + j], g_xh[(size_t)r0 * F + j] * W0);
            atomicAdd(&g_agg[(size_t)c1 * F + j], g_xh[(size_t)r1 * F + j] * W1);
        }
        __syncthreads();
    }
}

// ---------------- node update: h += ssp(agg@cf_w2+b2) @ lin_w + lin_b ----------------
#define SMEM_UPD ((TNU * H + F * H + H * H + 2 * H) * 4)
__global__ __launch_bounds__(NT, 1) void k_update(
    const float* __restrict__ w2, const float* __restrict__ b2,
    const float* __restrict__ lw, const float* __restrict__ lb)
{
    extern __shared__ float sm[];
    float* tile = sm;                // TNU*H = 8192 floats (union agg | t)
    float* w2s = tile + TNU * H;     // F*H
    float* lws = w2s + F * H;        // H*H
    float* b2s = lws + H * H;        // H
    float* lbs = b2s + H;            // H
    int tid = threadIdx.x;
    int j = tid & 127;
    int grp = tid >> 7;
    int p0 = grp * NPAIRU;
    for (int i = tid; i < F * H; i += NT) w2s[i] = w2[i];
    for (int i = tid; i < H * H; i += NT) lws[i] = lw[i];
    if (tid < H) { b2s[tid] = b2[tid]; lbs[tid] = lb[tid]; }
    __syncthreads();
    float bias2 = b2s[j], biasl = lbs[j];
    const int ntiles = N_NODES / TNU;
    for (int t = blockIdx.x; t < ntiles; t += gridDim.x) {
        int n0 = t * TNU;
        for (int idx = tid; idx < TNU * H; idx += NT) {
            int n = idx >> 7, k = idx & 127;
            int p = n >> 1, m = n & 1;
            tile[p * (2 * H) + 2 * k + m] = g_agg[(size_t)n0 * H + idx];
        }
        __syncthreads();
        u64 acc[NPAIRU];
        u64 binit = dup2(bias2);
        #pragma unroll
        for (int p = 0; p < NPAIRU; p++) acc[p] = binit;
        const ulonglong2* a2 = (const ulonglong2*)tile;   // [32][F/2]
        #pragma unroll 1
        for (int k2 = 0; k2 < F / 2; k2++) {
            u64 wk0 = dup2(w2s[(2 * k2 + 0) * H + j]);
            u64 wk1 = dup2(w2s[(2 * k2 + 1) * H + j]);
            #pragma unroll
            for (int p = 0; p < NPAIRU; p++) {
                ulonglong2 a = a2[(p0 + p) * (F / 2) + k2];
                fma2(acc[p], a.x, wk0);
                fma2(acc[p], a.y, wk1);
            }
        }
        __syncthreads();
        u64* tl2 = (u64*)tile;
        #pragma unroll
        for (int p = 0; p < NPAIRU; p++) {
            float lo, hi; unpack2(acc[p], lo, hi);
            tl2[(p0 + p) * H + j] = pack2(ssp(lo), ssp(hi));
        }
        __syncthreads();
        u64 binitl = dup2(biasl);
        #pragma unroll
        for (int p = 0; p < NPAIRU; p++) acc[p] = binitl;
        const ulonglong2* t2 = (const ulonglong2*)tile;
        #pragma unroll 1
        for (int k2 = 0; k2 < H / 2; k2++) {
            u64 wk0 = dup2(lws[(2 * k2 + 0) * H + j]);
            u64 wk1 = dup2(lws[(2 * k2 + 1) * H + j]);
            #pragma unroll
            for (int p = 0; p < NPAIRU; p++) {
                ulonglong2 a = t2[(p0 + p) * (H / 2) + k2];
                fma2(acc[p], a.x, wk0);
                fma2(acc[p], a.y, wk1);
            }
        }
        #pragma unroll
        for (int p = 0; p < NPAIRU; p++) {
            float lo, hi; unpack2(acc[p], lo, hi);
            int n_g = n0 + (p0 + p) * 2;
            g_h[(size_t)n_g * H + j] += lo;
            g_h[(size_t)(n_g + 1) * H + j] += hi;
        }
        __syncthreads();
    }
}

// ---------------- readout ----------------
#define H2 64
#define SMEM_RO ((H * H2 + H2 + H2 + TN * H + TN * 65) * 4)
__global__ __launch_bounds__(128) void k_readout(
    const float* __restrict__ w1, const float* __restrict__ b1,
    const float* __restrict__ w2, const float* __restrict__ b2,
    const int* __restrict__ batch, float* __restrict__ out)
{
    extern __shared__ float sm[];
    float* w1s = sm;                 // H*H2
    float* b1s = w1s + H * H2;       // H2
    float* w2s = b1s + H2;           // H2
    float* tile = w2s + H2;          // TN*H
    float* sbuf = tile + TN * H;     // TN*65
    int j = threadIdx.x;
    for (int i = j; i < H * H2; i += 128) w1s[i] = w1[i];
    if (j < H2) { b1s[j] = b1[j]; w2s[j] = w2[j]; }
    float b2v = b2[0];
    __syncthreads();
    const int ntiles = N_NODES / TN;
    for (int t = blockIdx.x; t < ntiles; t += gridDim.x) {
        int n0 = t * TN;
        for (int i = j; i < TN * H; i += 128) tile[i] = g_h[(size_t)n0 * H + i];
        __syncthreads();
        if (j < H2) {
            float acc[TN];
            #pragma unroll
            for (int n = 0; n < TN; n++) acc[n] = b1s[j];
            #pragma unroll 1
            for (int k4 = 0; k4 < H / 4; k4++) {
                float wa = w1s[(4 * k4 + 0) * H2 + j];
                float wb = w1s[(4 * k4 + 1) * H2 + j];
                float wc = w1s[(4 * k4 + 2) * H2 + j];
                float wd = w1s[(4 * k4 + 3) * H2 + j];
                #pragma unroll
                for (int n = 0; n < TN; n++) {
                    float4 a = *(const float4*)&tile[n * H + 4 * k4];
                    acc[n] = fmaf(a.x, wa, fmaf(a.y, wb, fmaf(a.z, wc, fmaf(a.w, wd, acc[n]))));
                }
            }
            #pragma unroll
            for (int n = 0; n < TN; n++) sbuf[n * 65 + j] = ssp(acc[n]);
        }
        __syncthreads();
        if (j < TN) {
            int n = j;
            float v = b2v;
            #pragma unroll 1
            for (int q = 0; q < H2; q++) v += sbuf[n * 65 + q] * w2s[q];
            atomicAdd(&out[batch[n0 + n]], v);
        }
        __syncthreads();
    }
}

__global__ void k_zero_out(float* out) {
    if (threadIdx.x < NGRAPH) out[threadIdx.x] = 0.0f;
}
__global__ void k_sigmoid(float* out) {
    if (threadIdx.x < NGRAPH) {
        float v = out[threadIdx.x];
        out[threadIdx.x] = 1.0f / (1.0f + __expf(-v));
    }
}

// ---------------- host launcher ----------------
extern "C" void kernel_launch(void* const* d_in, const int* in_sizes, int n_in,
                              void* d_out, int out_size) {
    const int*   z      = (const int*)d_in[0];
    const float* pos    = (const float*)d_in[1];
    const int*   ei     = (const int*)d_in[2];
    const int*   batch  = (const int*)d_in[3];
    const float* emb    = (const float*)d_in[4];
    const float* mlp_w1 = (const float*)d_in[5];
    const float* mlp_b1 = (const float*)d_in[6];
    const float* mlp_w2 = (const float*)d_in[7];
    const float* mlp_b2 = (const float*)d_in[8];
    const float* cf_w1  = (const float*)d_in[9];
    const float* cf_w2  = (const float*)d_in[10];
    const float* cf_b2  = (const float*)d_in[11];
    const float* lin_w  = (const float*)d_in[12];
    const float* lin_b  = (const float*)d_in[13];
    const float* out_w1 = (const float*)d_in[14];
    const float* out_b1 = (const float*)d_in[15];
    const float* out_w2 = (const float*)d_in[16];
    const float* out_b2 = (const float*)d_in[17];
    float* out = (float*)d_out;

    cudaFuncSetAttribute((const void*)k_edge,    cudaFuncAttributeMaxDynamicSharedMemorySize, SMEM_EDGE);
    cudaFuncSetAttribute((const void*)k_xh,      cudaFuncAttributeMaxDynamicSharedMemorySize, SMEM_XH);
    cudaFuncSetAttribute((const void*)k_update,  cudaFuncAttributeMaxDynamicSharedMemorySize, SMEM_UPD);
    cudaFuncSetAttribute((const void*)k_readout, cudaFuncAttributeMaxDynamicSharedMemorySize, SMEM_RO);

    k_init_h<<<(N_NODES * H) / 256, 256>>>(z, emb);
    k_geom<<<N_EDGES / 128, 128>>>(pos, ei);

    for (int l = 0; l < L; l++) {
        k_xh<<<296, NT, SMEM_XH>>>(cf_w1 + (size_t)l * H * F);
        k_edge<<<296, NT, SMEM_EDGE>>>(mlp_w1 + (size_t)l * G * F,
                                       mlp_b1 + (size_t)l * F,
                                       mlp_w2 + (size_t)l * F * F,
                                       mlp_b2 + (size_t)l * F,
                                       ei);
        k_update<<<148, NT, SMEM_UPD>>>(cf_w2 + (size_t)l * F * H,
                                        cf_b2 + (size_t)l * H,
                                        lin_w + (size_t)l * H * H,
                                        lin_b + (size_t)l * H);
    }

    k_zero_out<<<1, 32>>>(out);
    k_readout<<<296, 128, SMEM_RO>>>(out_w1, out_b1, out_w2, out_b2, batch, out);
    k_sigmoid<<<1, 32>>>(out);
}

// round 6
// speedup vs baseline: 1.9522x; 1.9522x over previous
#include <cuda_runtime.h>
#include <math.h>

#define N_NODES 16384
#define N_EDGES 262144
#define H 128
#define F 128
#define G 50
#define GP 52          // padded gaussians (even, 13 float4s)
#define L 6
#define NGRAPH 16
#define TE 32          // edges per tile
#define TN 32          // nodes per tile
#define NT 256         // threads: 4 groups x 64 channel-pairs
#define EPG 8          // edges (or nodes) per group

// ---------------- device scratch ----------------
__device__ float  g_ea[(size_t)N_EDGES * GP];    // row-major [E][52]
__device__ float  g_C[N_EDGES];
__device__ float  g_h[(size_t)N_NODES * H];      // plain [N][128]
__device__ float2 g_xh2[(size_t)N_NODES * 64];   // pair layout: [n][j] = (ch j, ch j+64)
__device__ float2 g_agg2[(size_t)N_NODES * 64];  // same pair layout

__device__ __forceinline__ float ssp(float x) {
    return log1pf(__expf(-fabsf(x))) + fmaxf(x, 0.0f) - 0.69314718055994531f;
}
__device__ __forceinline__ void red2(float2* addr, float x, float y) {
    asm volatile("red.global.add.v2.f32 [%0], {%1, %2};"
                 :: "l"(addr), "f"(x), "f"(y) : "memory");
}

// ---------------- init: h = emb[z] ----------------
__global__ void k_init_h(const int* __restrict__ z, const float* __restrict__ emb) {
    int i = blockIdx.x * blockDim.x + threadIdx.x;
    if (i < N_NODES * H) {
        int n = i >> 7, j = i & 127;
        g_h[i] = emb[z[n] * H + j];
    }
}

// ---------------- geometry: ew, C, ea ----------------
__global__ void k_geom(const float* __restrict__ pos, const int* __restrict__ ei) {
    __shared__ float ew_sh[128];
    int e = blockIdx.x * 128 + threadIdx.x;
    const int* row = ei;
    const int* col = ei + N_EDGES;
    int r = row[e], c = col[e];
    float dx = pos[r * 3 + 0] - pos[c * 3 + 0];
    float dy = pos[r * 3 + 1] - pos[c * 3 + 1];
    float dz = pos[r * 3 + 2] - pos[c * 3 + 2];
    dx -= rintf(dx * 0.2f) * 5.0f;
    dy -= rintf(dy * 0.2f) * 5.0f;
    dz -= rintf(dz * 0.2f) * 5.0f;
    float ew = sqrtf(dx * dx + dy * dy + dz * dz);
    ew_sh[threadIdx.x] = ew;
    float Cv = (ew < 10.0f) ? 0.5f * (cosf(ew * 0.31415926535897932f) + 1.0f) : 0.0f;
    g_C[e] = Cv;
    __syncthreads();
    const float step = 10.0f / 49.0f;
    const float coeff = -0.5f / (step * step);
    size_t base = (size_t)blockIdx.x * 128 * GP;
    for (int i = threadIdx.x; i < 128 * GP; i += 128) {
        int le = i / GP, k = i - le * GP;
        float v = 0.0f;
        if (k < G) {
            float d = ew_sh[le] - (float)k * step;
            v = __expf(coeff * d * d);
        }
        g_ea[base + i] = v;
    }
}

// ---------------- xh = h @ cf_w1[l] (pair layout out); zero agg ----------------
#define SMEM_XH ((TN * H + H * 64 * 2) * 4)
__global__ __launch_bounds__(NT, 2) void k_xh(const float* __restrict__ w) {
    extern __shared__ float sm[];
    float*  tile = sm;                       // TN*H = 4096
    float2* wp   = (float2*)(tile + TN * H); // [H][64] pairs
    int tid = threadIdx.x;
    int j = tid & 63;
    int grp = tid >> 6;
    for (int i = tid; i < H * 64; i += NT) {
        int k = i >> 6, jj = i & 63;
        wp[i] = make_float2(w[k * F + jj], w[k * F + jj + 64]);
    }
    __syncthreads();
    const int ntiles = N_NODES / TN;
    for (int t = blockIdx.x; t < ntiles; t += gridDim.x) {
        int n0 = t * TN;
        for (int i = tid; i < TN * H; i += NT) tile[i] = g_h[(size_t)n0 * H + i];
        __syncthreads();
        float aL[EPG], aH[EPG];
        #pragma unroll
        for (int n = 0; n < EPG; n++) { aL[n] = 0.0f; aH[n] = 0.0f; }
        const float4* t4 = (const float4*)tile;   // [32][32]
        #pragma unroll 1
        for (int k4 = 0; k4 < H / 4; k4++) {
            float2 w0 = wp[(4 * k4 + 0) * 64 + j];
            float2 w1 = wp[(4 * k4 + 1) * 64 + j];
            float2 w2 = wp[(4 * k4 + 2) * 64 + j];
            float2 w3 = wp[(4 * k4 + 3) * 64 + j];
            #pragma unroll
            for (int n = 0; n < EPG; n++) {
                float4 a = t4[(grp * EPG + n) * (H / 4) + k4];
                aL[n] = fmaf(a.x, w0.x, fmaf(a.y, w1.x, fmaf(a.z, w2.x, fmaf(a.w, w3.x, aL[n]))));
                aH[n] = fmaf(a.x, w0.y, fmaf(a.y, w1.y, fmaf(a.z, w2.y, fmaf(a.w, w3.y, aH[n]))));
            }
        }
        #pragma unroll
        for (int n = 0; n < EPG; n++) {
            int ng = n0 + grp * EPG + n;
            g_xh2[(size_t)ng * 64 + j] = make_float2(aL[n], aH[n]);
            g_agg2[(size_t)ng * 64 + j] = make_float2(0.0f, 0.0f);
        }
        __syncthreads();
    }
}

// ---------------- fused edge kernel (2 channels x 8 edges per thread) ----------------
#define SMEM_EDGE ((TE * F + GP * 64 * 2 + F * 64 * 2 + 2 * F + 3 * TE) * 4)
__global__ __launch_bounds__(NT, 2) void k_edge(
    const float* __restrict__ w1, const float* __restrict__ b1,
    const float* __restrict__ w2, const float* __restrict__ b2,
    const int* __restrict__ ei)
{
    extern __shared__ float sm[];
    float*  tile = sm;                         // union: ea [32][52]=1664 | t1 [32][128]=4096
    float2* w1p  = (float2*)(tile + TE * F);   // [52][64] pairs
    float2* w2p  = w1p + GP * 64;              // [128][64] pairs
    float*  b1s  = (float*)(w2p + F * 64);     // 128
    float*  b2s  = b1s + F;                    // 128
    int*   sRow  = (int*)(b2s + F);            // 32
    int*   sCol  = sRow + TE;                  // 32
    float* sC    = (float*)(sCol + TE);        // 32
    int tid = threadIdx.x;
    int j = tid & 63;
    int grp = tid >> 6;
    for (int i = tid; i < GP * 64; i += NT) {
        int k = i >> 6, jj = i & 63;
        float2 v = make_float2(0.0f, 0.0f);
        if (k < G) v = make_float2(w1[k * F + jj], w1[k * F + jj + 64]);
        w1p[i] = v;
    }
    for (int i = tid; i < F * 64; i += NT) {
        int k = i >> 6, jj = i & 63;
        w2p[i] = make_float2(w2[k * F + jj], w2[k * F + jj + 64]);
    }
    if (tid < F) { b1s[tid] = b1[tid]; b2s[tid] = b2[tid]; }
    const int* row = ei;
    const int* col = ei + N_EDGES;
    __syncthreads();
    float b1L = b1s[j], b1H = b1s[j + 64];
    float b2L = b2s[j], b2H = b2s[j + 64];
    const int ntiles = N_EDGES / TE;
    for (int t = blockIdx.x; t < ntiles; t += gridDim.x) {
        int e0 = t * TE;
        {   // stage ea tile: 1664 contiguous floats
            const float4* src = (const float4*)(g_ea + (size_t)t * (TE * GP));
            float4* dst = (float4*)tile;
            #pragma unroll
            for (int i = tid; i < (TE * GP) / 4; i += NT) dst[i] = src[i];
        }
        if (tid < TE) {
            sRow[tid] = row[e0 + tid];
            sCol[tid] = col[e0 + tid];
            sC[tid]   = g_C[e0 + tid];
        }
        __syncthreads();
        float aL[EPG], aH[EPG];
        #pragma unroll
        for (int e = 0; e < EPG; e++) { aL[e] = b1L; aH[e] = b1H; }
        const float4* ea4 = (const float4*)tile;   // [32][13]
        #pragma unroll 1
        for (int k4 = 0; k4 < GP / 4; k4++) {
            float2 w0 = w1p[(4 * k4 + 0) * 64 + j];
            float2 wb = w1p[(4 * k4 + 1) * 64 + j];
            float2 wc = w1p[(4 * k4 + 2) * 64 + j];
            float2 wd = w1p[(4 * k4 + 3) * 64 + j];
            #pragma unroll
            for (int e = 0; e < EPG; e++) {
                float4 a = ea4[(grp * EPG + e) * (GP / 4) + k4];
                aL[e] = fmaf(a.x, w0.x, fmaf(a.y, wb.x, fmaf(a.z, wc.x, fmaf(a.w, wd.x, aL[e]))));
                aH[e] = fmaf(a.x, w0.y, fmaf(a.y, wb.y, fmaf(a.z, wc.y, fmaf(a.w, wd.y, aH[e]))));
            }
        }
        __syncthreads();   // all GEMM1 reads of ea done before t1 overwrite
        #pragma unroll
        for (int e = 0; e < EPG; e++) {
            int le = grp * EPG + e;
            tile[le * F + j]      = ssp(aL[e]);
            tile[le * F + j + 64] = ssp(aH[e]);
        }
        __syncthreads();
        #pragma unroll
        for (int e = 0; e < EPG; e++) { aL[e] = b2L; aH[e] = b2H; }
        const float4* t4 = (const float4*)tile;    // [32][32]
        #pragma unroll 1
        for (int k4 = 0; k4 < F / 4; k4++) {
            float2 w0 = w2p[(4 * k4 + 0) * 64 + j];
            float2 wb = w2p[(4 * k4 + 1) * 64 + j];
            float2 wc = w2p[(4 * k4 + 2) * 64 + j];
            float2 wd = w2p[(4 * k4 + 3) * 64 + j];
            #pragma unroll
            for (int e = 0; e < EPG; e++) {
                float4 a = t4[(grp * EPG + e) * (F / 4) + k4];
                aL[e] = fmaf(a.x, w0.x, fmaf(a.y, wb.x, fmaf(a.z, wc.x, fmaf(a.w, wd.x, aL[e]))));
                aH[e] = fmaf(a.x, w0.y, fmaf(a.y, wb.y, fmaf(a.z, wc.y, fmaf(a.w, wd.y, aH[e]))));
            }
        }
        // epilogue: gather xh2[row], modulate by C, vector-red into agg2[col]
        #pragma unroll
        for (int e = 0; e < EPG; e++) {
            int le = grp * EPG + e;
            float Cv = sC[le];
            float2 xv = g_xh2[(size_t)sRow[le] * 64 + j];
            float2* ap = &g_agg2[(size_t)sCol[le] * 64 + j];
            red2(ap, xv.x * (aL[e] * Cv), xv.y * (aH[e] * Cv));
        }
        __syncthreads();
    }
}

// ---------------- node update: h += ssp(agg@cf_w2+b2) @ lin_w + lin_b ----------------
#define SMEM_UPD ((TN * H + F * 64 * 2 + H * 64 * 2 + 2 * H) * 4)
__global__ __launch_bounds__(NT, 1) void k_update(
    const float* __restrict__ w2, const float* __restrict__ b2,
    const float* __restrict__ lw, const float* __restrict__ lb)
{
    extern __shared__ float sm[];
    float*  tile = sm;                         // [32][128] union agg | ssp
    float2* w2p  = (float2*)(tile + TN * H);   // [128][64]
    float2* lwp  = w2p + F * 64;               // [128][64]
    float*  b2s  = (float*)(lwp + H * 64);     // 128
    float*  lbs  = b2s + H;                    // 128
    int tid = threadIdx.x;
    int j = tid & 63;
    int grp = tid >> 6;
    for (int i = tid; i < F * 64; i += NT) {
        int k = i >> 6, jj = i & 63;
        w2p[i] = make_float2(w2[k * H + jj], w2[k * H + jj + 64]);
        lwp[i] = make_float2(lw[k * H + jj], lw[k * H + jj + 64]);
    }
    if (tid < H) { b2s[tid] = b2[tid]; lbs[tid] = lb[tid]; }
    __syncthreads();
    float b2L = b2s[j], b2H = b2s[j + 64];
    float blL = lbs[j], blH = lbs[j + 64];
    const int ntiles = N_NODES / TN;
    for (int t = blockIdx.x; t < ntiles; t += gridDim.x) {
        int n0 = t * TN;
        for (int i = tid; i < TN * 64; i += NT) {
            int n = i >> 6, jj = i & 63;
            float2 v = g_agg2[(size_t)(n0 + n) * 64 + jj];
            tile[n * H + jj]      = v.x;
            tile[n * H + jj + 64] = v.y;
        }
        __syncthreads();
        float aL[EPG], aH[EPG];
        #pragma unroll
        for (int n = 0; n < EPG; n++) { aL[n] = b2L; aH[n] = b2H; }
        const float4* t4 = (const float4*)tile;
        #pragma unroll 1
        for (int k4 = 0; k4 < F / 4; k4++) {
            float2 w0 = w2p[(4 * k4 + 0) * 64 + j];
            float2 wb = w2p[(4 * k4 + 1) * 64 + j];
            float2 wc = w2p[(4 * k4 + 2) * 64 + j];
            float2 wd = w2p[(4 * k4 + 3) * 64 + j];
            #pragma unroll
            for (int n = 0; n < EPG; n++) {
                float4 a = t4[(grp * EPG + n) * (H / 4) + k4];
                aL[n] = fmaf(a.x, w0.x, fmaf(a.y, wb.x, fmaf(a.z, wc.x, fmaf(a.w, wd.x, aL[n]))));
                aH[n] = fmaf(a.x, w0.y, fmaf(a.y, wb.y, fmaf(a.z, wc.y, fmaf(a.w, wd.y, aH[n]))));
            }
        }
        __syncthreads();
        #pragma unroll
        for (int n = 0; n < EPG; n++) {
            int ln = grp * EPG + n;
            tile[ln * H + j]      = ssp(aL[n]);
            tile[ln * H + j + 64] = ssp(aH[n]);
        }
        __syncthreads();
        #pragma unroll
        for (int n = 0; n < EPG; n++) { aL[n] = blL; aH[n] = blH; }
        #pragma unroll 1
        for (int k4 = 0; k4 < H / 4; k4++) {
            float2 w0 = lwp[(4 * k4 + 0) * 64 + j];
            float2 wb = lwp[(4 * k4 + 1) * 64 + j];
            float2 wc = lwp[(4 * k4 + 2) * 64 + j];
            float2 wd = lwp[(4 * k4 + 3) * 64 + j];
            #pragma unroll
            for (int n = 0; n < EPG; n++) {
                float4 a = t4[(grp * EPG + n) * (H / 4) + k4];
                aL[n] = fmaf(a.x, w0.x, fmaf(a.y, wb.x, fmaf(a.z, wc.x, fmaf(a.w, wd.x, aL[n]))));
                aH[n] = fmaf(a.x, w0.y, fmaf(a.y, wb.y, fmaf(a.z, wc.y, fmaf(a.w, wd.y, aH[n]))));
            }
        }
        #pragma unroll
        for (int n = 0; n < EPG; n++) {
            int ng = n0 + grp * EPG + n;
            g_h[(size_t)ng * H + j]      += aL[n];
            g_h[(size_t)ng * H + j + 64] += aH[n];
        }
        __syncthreads();
    }
}

// ---------------- readout ----------------
#define H2 64
#define SMEM_RO ((H * H2 + H2 + H2 + TN * H + TN * 65) * 4)
__global__ __launch_bounds__(128) void k_readout(
    const float* __restrict__ w1, const float* __restrict__ b1,
    const float* __restrict__ w2, const float* __restrict__ b2,
    const int* __restrict__ batch, float* __restrict__ out)
{
    extern __shared__ float sm[];
    float* w1s = sm;                 // H*H2
    float* b1s = w1s + H * H2;       // H2
    float* w2s = b1s + H2;           // H2
    float* tile = w2s + H2;          // TN*H
    float* sbuf = tile + TN * H;     // TN*65
    int j = threadIdx.x;
    for (int i = j; i < H * H2; i += 128) w1s[i] = w1[i];
    if (j < H2) { b1s[j] = b1[j]; w2s[j] = w2[j]; }
    float b2v = b2[0];
    __syncthreads();
    const int ntiles = N_NODES / TN;
    for (int t = blockIdx.x; t < ntiles; t += gridDim.x) {
        int n0 = t * TN;
        for (int i = j; i < TN * H; i += 128) tile[i] = g_h[(size_t)n0 * H + i];
        __syncthreads();
        if (j < H2) {
            float acc[TN];
            #pragma unroll
            for (int n = 0; n < TN; n++) acc[n] = b1s[j];
            #pragma unroll 1
            for (int k4 = 0; k4 < H / 4; k4++) {
                float wa = w1s[(4 * k4 + 0) * H2 + j];
                float wb = w1s[(4 * k4 + 1) * H2 + j];
                float wc = w1s[(4 * k4 + 2) * H2 + j];
                float wd = w1s[(4 * k4 + 3) * H2 + j];
                #pragma unroll
                for (int n = 0; n < TN; n++) {
                    float4 a = *(const float4*)&tile[n * H + 4 * k4];
                    acc[n] = fmaf(a.x, wa, fmaf(a.y, wb, fmaf(a.z, wc, fmaf(a.w, wd, acc[n]))));
                }
            }
            #pragma unroll
            for (int n = 0; n < TN; n++) sbuf[n * 65 + j] = ssp(acc[n]);
        }
        __syncthreads();
        if (j < TN) {
            int n = j;
            float v = b2v;
            #pragma unroll 1
            for (int q = 0; q < H2; q++) v += sbuf[n * 65 + q] * w2s[q];
            atomicAdd(&out[batch[n0 + n]], v);
        }
        __syncthreads();
    }
}

__global__ void k_zero_out(float* out) {
    if (threadIdx.x < NGRAPH) out[threadIdx.x] = 0.0f;
}
__global__ void k_sigmoid(float* out) {
    if (threadIdx.x < NGRAPH) {
        float v = out[threadIdx.x];
        out[threadIdx.x] = 1.0f / (1.0f + __expf(-v));
    }
}

// ---------------- host launcher ----------------
extern "C" void kernel_launch(void* const* d_in, const int* in_sizes, int n_in,
                              void* d_out, int out_size) {
    const int*   z      = (const int*)d_in[0];
    const float* pos    = (const float*)d_in[1];
    const int*   ei     = (const int*)d_in[2];
    const int*   batch  = (const int*)d_in[3];
    const float* emb    = (const float*)d_in[4];
    const float* mlp_w1 = (const float*)d_in[5];
    const float* mlp_b1 = (const float*)d_in[6];
    const float* mlp_w2 = (const float*)d_in[7];
    const float* mlp_b2 = (const float*)d_in[8];
    const float* cf_w1  = (const float*)d_in[9];
    const float* cf_w2  = (const float*)d_in[10];
    const float* cf_b2  = (const float*)d_in[11];
    const float* lin_w  = (const float*)d_in[12];
    const float* lin_b  = (const float*)d_in[13];
    const float* out_w1 = (const float*)d_in[14];
    const float* out_b1 = (const float*)d_in[15];
    const float* out_w2 = (const float*)d_in[16];
    const float* out_b2 = (const float*)d_in[17];
    float* out = (float*)d_out;

    cudaFuncSetAttribute((const void*)k_edge,    cudaFuncAttributeMaxDynamicSharedMemorySize, SMEM_EDGE);
    cudaFuncSetAttribute((const void*)k_xh,      cudaFuncAttributeMaxDynamicSharedMemorySize, SMEM_XH);
    cudaFuncSetAttribute((const void*)k_update,  cudaFuncAttributeMaxDynamicSharedMemorySize, SMEM_UPD);
    cudaFuncSetAttribute((const void*)k_readout, cudaFuncAttributeMaxDynamicSharedMemorySize, SMEM_RO);

    k_init_h<<<(N_NODES * H) / 256, 256>>>(z, emb);
    k_geom<<<N_EDGES / 128, 128>>>(pos, ei);

    for (int l = 0; l < L; l++) {
        k_xh<<<296, NT, SMEM_XH>>>(cf_w1 + (size_t)l * H * F);
        k_edge<<<296, NT, SMEM_EDGE>>>(mlp_w1 + (size_t)l * G * F,
                                       mlp_b1 + (size_t)l * F,
                                       mlp_w2 + (size_t)l * F * F,
                                       mlp_b2 + (size_t)l * F,
                                       ei);
        k_update<<<148, NT, SMEM_UPD>>>(cf_w2 + (size_t)l * F * H,
                                        cf_b2 + (size_t)l * H,
                                        lin_w + (size_t)l * H * H,
                                        lin_b + (size_t)l * H);
    }

    k_zero_out<<<1, 32>>>(out);
    k_readout<<<296, 128, SMEM_RO>>>(out_w1, out_b1, out_w2, out_b2, batch, out);
    k_sigmoid<<<1, 32>>>(out);
}